// round 6
// baseline (speedup 1.0000x reference)
#include <cuda_runtime.h>

// Shapes (fixed by the problem)
#define B_    8
#define T_    12
#define N_    512
#define D_    128
#define H_    8
#define HD_   16
#define X_    64            // H_*B_
#define KTOP_ 153           // int(512*0.3)
#define ATTN_ELEMS 201326592ll   // 64*12*512*512

#define FULLMASK 0xffffffffu

// Scratch: projected q,k in split-head layout [x][t][n][hd]
__device__ float g_qs[X_*T_*N_*HD_];
__device__ float g_ks[X_*T_*N_*HD_];

// ---------------------------------------------------------------------------
// Kernel 1: fused projections. blockIdx.y selects (q|k|v). 32 rows per block.
// W staged in smem with intra-row chunk permutation phys = 4*cg + 32*c + w so
// the compute-phase float4 reads are bank-conflict-free across the 8 col-groups.
// q,k go to scratch in split-head layout; v goes straight to the output buffer.
// ---------------------------------------------------------------------------
__global__ __launch_bounds__(256) void proj_kernel(
    const float* __restrict__ qin, const float* __restrict__ kin,
    const float* __restrict__ vin,
    const float* __restrict__ Wq, const float* __restrict__ bq,
    const float* __restrict__ Wk, const float* __restrict__ bk,
    const float* __restrict__ Wv, const float* __restrict__ bv,
    float* __restrict__ out_v)
{
    extern __shared__ float sh[];
    float* shW = sh;            // 128*128 floats, swizzled within rows
    float* shA = sh + 16384;    // 32 rows * 132 (padded) floats

    const float* in; const float* W; const float* bias; float* dst;
    if (blockIdx.y == 0)      { in = qin; W = Wq; bias = bq; dst = g_qs; }
    else if (blockIdx.y == 1) { in = kin; W = Wk; bias = bk; dst = g_ks; }
    else                      { in = vin; W = Wv; bias = bv; dst = out_v; }

    const int tid = threadIdx.x;

    // Load W (permuted): logical col = 16*cg + 4*c + w -> phys word 4*cg + 32*c + w
    for (int i = tid; i < 16384; i += 256) {
        int k = i >> 7, col = i & 127;
        int cg = col >> 4, c = (col >> 2) & 3, w = col & 3;
        shW[k*128 + cg*4 + c*32 + w] = W[i];
    }
    const size_t base_row = (size_t)blockIdx.x * 32;
    for (int i = tid; i < 4096; i += 256) {
        int r = i >> 7, k = i & 127;
        shA[r*132 + k] = in[base_row*128 + i];
    }
    __syncthreads();

    const int r  = tid >> 3;   // 0..31  (row within tile)
    const int cg = tid & 7;    // 0..7   (column group == head index)

    float acc[16];
    #pragma unroll
    for (int j = 0; j < 16; j++) acc[j] = __ldg(bias + cg*16 + j);

    const float* arow  = shA + r*132;
    const float* wbase = shW + cg*4;
    #pragma unroll 4
    for (int k = 0; k < 128; k++) {
        const float a = arow[k];
        const float4 w0 = *(const float4*)(wbase + k*128);
        const float4 w1 = *(const float4*)(wbase + k*128 + 32);
        const float4 w2 = *(const float4*)(wbase + k*128 + 64);
        const float4 w3 = *(const float4*)(wbase + k*128 + 96);
        acc[ 0] += a*w0.x; acc[ 1] += a*w0.y; acc[ 2] += a*w0.z; acc[ 3] += a*w0.w;
        acc[ 4] += a*w1.x; acc[ 5] += a*w1.y; acc[ 6] += a*w1.z; acc[ 7] += a*w1.w;
        acc[ 8] += a*w2.x; acc[ 9] += a*w2.y; acc[10] += a*w2.z; acc[11] += a*w2.w;
        acc[12] += a*w3.x; acc[13] += a*w3.y; acc[14] += a*w3.z; acc[15] += a*w3.w;
    }

    // Split-head destination: x = h*B + b, h == cg, hd = j
    const int row = (int)base_row + r;
    const int b   = row / (T_*N_);
    const int rem = row - b*(T_*N_);
    const int t   = rem / N_;
    const int n   = rem - t*N_;
    const size_t di = ((((size_t)cg*B_ + b)*T_ + t)*N_ + n)*HD_;
    *(float4*)(dst + di     ) = make_float4(acc[ 0],acc[ 1],acc[ 2],acc[ 3]);
    *(float4*)(dst + di +  4) = make_float4(acc[ 4],acc[ 5],acc[ 6],acc[ 7]);
    *(float4*)(dst + di +  8) = make_float4(acc[ 8],acc[ 9],acc[10],acc[11]);
    *(float4*)(dst + di + 12) = make_float4(acc[12],acc[13],acc[14],acc[15]);
}

// ---------------------------------------------------------------------------
// Kernel 2: scores + softmax + exact top-k threshold.
// Block: 256 thr (8 warps) = one (x,t), 32 rows (4 rows/warp, reg-blocked).
// K tile in smem, row stride 20 floats; lane owns m = lane + 32*j (j=0..15):
// the LDS.128 phase count then equals the data-volume minimum.
// Selection: warp radix-select on flipped float bits of the (scaled) scores,
// which is order-equivalent to selecting on softmax outputs.
// ---------------------------------------------------------------------------
__device__ __forceinline__ unsigned flipf(float f) {
    unsigned u = __float_as_uint(f);
    return u ^ ((unsigned)((int)u >> 31) | 0x80000000u);
}

__global__ __launch_bounds__(256, 2) void attn_kernel(
    const float* __restrict__ adp, float* __restrict__ out)
{
    extern __shared__ float sh[];
    float* Ksh  = sh;                      // 512 * 20 floats = 40960 B
    int*   hist = (int*)(sh + 512*20);     // 8 warps * 256 bins = 8192 B

    const int xt   = blockIdx.y;           // 0..767 : x = xt/12, t = xt%12
    const int tile = blockIdx.x;           // 0..15  : 32 rows each
    const int tid  = threadIdx.x;
    const int lane = tid & 31;
    const int wid  = tid >> 5;
    const size_t xtbase = (size_t)xt * N_; // row base in (x,t) space

    // Stage K tile (512 x 16 floats) into padded smem
    const float* gk = g_ks + xtbase * HD_;
    for (int i = tid; i < 2048; i += 256) {
        int m = i >> 2, c = i & 3;
        float4 v = __ldg((const float4*)(gk + (size_t)i*4));
        *(float4*)(Ksh + m*20 + c*4) = v;
    }
    __syncthreads();

    const int n0 = tile*32 + wid*4;
    const float* gq = g_qs + (xtbase + n0) * HD_;

    // ---- score phase: 4 rows x 16 m-values per lane, d split in two sweeps
    float s[4][16];
    #pragma unroll
    for (int r = 0; r < 4; r++)
        #pragma unroll
        for (int j = 0; j < 16; j++) s[r][j] = 0.f;

    #pragma unroll
    for (int hh = 0; hh < 2; hh++) {
        float4 qa[4], qb[4];
        #pragma unroll
        for (int r = 0; r < 4; r++) {
            qa[r] = *(const float4*)(gq + r*16 + 8*hh);
            qb[r] = *(const float4*)(gq + r*16 + 8*hh + 4);
        }
        #pragma unroll
        for (int j = 0; j < 16; j++) {
            const int m = lane + 32*j;
            const float* kr = Ksh + m*20 + 8*hh;
            const float4 ka = *(const float4*)kr;
            const float4 kb = *(const float4*)(kr + 4);
            #pragma unroll
            for (int r = 0; r < 4; r++) {
                s[r][j] += qa[r].x*ka.x + qa[r].y*ka.y + qa[r].z*ka.z + qa[r].w*ka.w
                         + qb[r].x*kb.x + qb[r].y*kb.y + qb[r].z*kb.z + qb[r].w*kb.w;
            }
        }
    }

    int* h = hist + wid*256;

    #pragma unroll 1
    for (int r = 0; r < 4; r++) {
        const int n = n0 + r;
        const float* arow = adp + n*N_;

        // finalize scores: s = dot/4 * adp[n][m]
        #pragma unroll
        for (int j = 0; j < 16; j++)
            s[r][j] = s[r][j] * 0.25f * __ldg(arow + lane + 32*j);

        // row max (for stable exp)
        float M = s[r][0];
        #pragma unroll
        for (int j = 1; j < 16; j++) M = fmaxf(M, s[r][j]);
        #pragma unroll
        for (int d = 16; d; d >>= 1) M = fmaxf(M, __shfl_xor_sync(FULLMASK, M, d));

        // ---- exact 153rd-largest via radix select on flipped bits
        int krm = KTOP_;
        unsigned prefix = 0, pmask = 0, kth = 0;
        for (int pass = 0; pass < 4; ++pass) {
            const int shift = 24 - 8*pass;
            #pragma unroll
            for (int bn = 0; bn < 8; bn++) h[lane*8 + bn] = 0;
            __syncwarp();
            // histogram with match-aggregated atomics
            #pragma unroll
            for (int j = 0; j < 16; j++) {
                unsigned u = flipf(s[r][j]);
                bool cand = ((u & pmask) == prefix);
                unsigned d = cand ? ((u >> shift) & 255u) : 0xffffffffu;
                unsigned grp = __match_any_sync(FULLMASK, d);
                unsigned leader = __ffs(grp) - 1u;
                if (cand && lane == leader) atomicAdd(&h[d], __popc(grp));
            }
            __syncwarp();
            // scan 256 bins (8 per lane, contiguous)
            int c[8]; int lsum = 0;
            #pragma unroll
            for (int bn = 0; bn < 8; bn++) { c[bn] = h[lane*8 + bn]; lsum += c[bn]; }
            int inc = lsum;
            #pragma unroll
            for (int d = 1; d < 32; d <<= 1) {
                int tv = __shfl_up_sync(FULLMASK, inc, d);
                if (lane >= d) inc += tv;
            }
            const int T   = __shfl_sync(FULLMASK, inc, 31);
            const int Pex = inc - lsum;
            const int lim = T - Pex - krm;   // pre[b] <= lim  <=>  count_ge(bin) >= kr
            int best = -1, Gloc = 0, cat = 0, pre = 0;
            #pragma unroll
            for (int bn = 0; bn < 8; bn++) {
                if (pre <= lim) { best = lane*8 + bn; Gloc = T - Pex - pre - c[bn]; cat = c[bn]; }
                pre += c[bn];
            }
            int Bb = best;
            #pragma unroll
            for (int d = 16; d; d >>= 1) Bb = max(Bb, __shfl_xor_sync(FULLMASK, Bb, d));
            const int L  = Bb >> 3;
            const int Gv = __shfl_sync(FULLMASK, Gloc, L);
            const int cv = __shfl_sync(FULLMASK, cat,  L);
            krm   -= Gv;
            prefix |= ((unsigned)(Bb & 255)) << shift;
            pmask  |= 0xffu << shift;
            if (pass == 3) { kth = prefix; break; }
            if (cv == 1) {  // unique key in the chosen bin -> gather it exactly
                unsigned candk = 0;
                #pragma unroll
                for (int j = 0; j < 16; j++) {
                    unsigned u = flipf(s[r][j]);
                    if ((u & pmask) == prefix) candk = u;
                }
                #pragma unroll
                for (int d = 16; d; d >>= 1) candk |= __shfl_xor_sync(FULLMASK, candk, d);
                kth = candk; break;
            }
        }

        // ---- softmax (single exp pass) + keep-mask + write
        unsigned keep = 0; float sum = 0.f;
        #pragma unroll
        for (int j = 0; j < 16; j++) {
            float sv = s[r][j];
            if (flipf(sv) >= kth) keep |= (1u << j);
            float p = __expf(sv - M);
            sum += p;
            s[r][j] = p;
        }
        #pragma unroll
        for (int d = 16; d; d >>= 1) sum += __shfl_xor_sync(FULLMASK, sum, d);
        const float inv = 1.0f / sum;

        float* orow = out + (xtbase + n) * N_;
        #pragma unroll
        for (int j = 0; j < 16; j++)
            orow[lane + 32*j] = ((keep >> j) & 1u) ? s[r][j] * inv : 0.0f;
    }
}

// ---------------------------------------------------------------------------
extern "C" void kernel_launch(void* const* d_in, const int* in_sizes, int n_in,
                              void* d_out, int out_size)
{
    const float* query = (const float*)d_in[0];
    const float* key   = (const float*)d_in[1];
    const float* value = (const float*)d_in[2];
    const float* adp   = (const float*)d_in[3];
    const float* Wq    = (const float*)d_in[4];
    const float* bq    = (const float*)d_in[5];
    const float* Wk    = (const float*)d_in[6];
    const float* bk    = (const float*)d_in[7];
    const float* Wv    = (const float*)d_in[8];
    const float* bv    = (const float*)d_in[9];

    float* out_attn = (float*)d_out;                 // (64,12,512,512)
    float* out_v    = (float*)d_out + ATTN_ELEMS;    // (64,12,512,16)

    const int proj_smem = (16384 + 32*132) * 4;      // 82432 B
    const int attn_smem = (512*20 + 8*256) * 4;      // 49152 B
    cudaFuncSetAttribute(proj_kernel, cudaFuncAttributeMaxDynamicSharedMemorySize, proj_smem);
    cudaFuncSetAttribute(attn_kernel, cudaFuncAttributeMaxDynamicSharedMemorySize, attn_smem);

    proj_kernel<<<dim3((B_*T_*N_)/32, 3), 256, proj_smem>>>(
        query, key, value, Wq, bq, Wk, bk, Wv, bv, out_v);
    attn_kernel<<<dim3(N_/32, X_*T_), 256, attn_smem>>>(adp, out_attn);
    (void)in_sizes; (void)n_in; (void)out_size;
}

// round 7
// speedup vs baseline: 1.7186x; 1.7186x over previous
#include <cuda_runtime.h>

// Shapes (fixed by the problem)
#define B_    8
#define T_    12
#define N_    512
#define D_    128
#define H_    8
#define HD_   16
#define X_    64            // H_*B_
#define KTOP_ 153           // int(512*0.3)
#define ATTN_ELEMS 201326592ll   // 64*12*512*512

#define FULLMASK 0xffffffffu

// Scratch: projected q,k in split-head layout [x][t][n][hd]
__device__ float g_qs[X_*T_*N_*HD_];
__device__ float g_ks[X_*T_*N_*HD_];

// ---------------------------------------------------------------------------
// order-preserving float<->uint key transforms
// ---------------------------------------------------------------------------
__device__ __forceinline__ unsigned flipf(float f) {
    unsigned u = __float_as_uint(f);
    return u ^ ((unsigned)((int)u >> 31) | 0x80000000u);
}
__device__ __forceinline__ float unflipf(unsigned u) {
    unsigned m = 0x80000000u | ~(unsigned)((int)u >> 31); // top=1 -> 0x80000000, top=0 -> 0xffffffff
    return __uint_as_float(u ^ m);
}

// ---------------------------------------------------------------------------
// Kernel 1: fused projections. blockIdx.y selects (q|k|v).
// 64 rows per block, 2 rows per thread (r and r+32) -> W smem reads amortized
// 2x and warp-broadcast across the 4 row-groups; FFMA-bound.
// W staged in smem with intra-row chunk permutation phys = 4*cg + 32*c + w so
// the compute-phase float4 reads are conflict-free across the 8 col-groups.
// ---------------------------------------------------------------------------
__global__ __launch_bounds__(256, 2) void proj_kernel(
    const float* __restrict__ qin, const float* __restrict__ kin,
    const float* __restrict__ vin,
    const float* __restrict__ Wq, const float* __restrict__ bq,
    const float* __restrict__ Wk, const float* __restrict__ bk,
    const float* __restrict__ Wv, const float* __restrict__ bv,
    float* __restrict__ out_v)
{
    extern __shared__ float sh[];
    float* shW = sh;            // 128*128 floats, swizzled within rows
    float* shA = sh + 16384;    // 64 rows * 129 (padded) floats

    const float* in; const float* W; const float* bias; float* dst;
    if (blockIdx.y == 0)      { in = qin; W = Wq; bias = bq; dst = g_qs; }
    else if (blockIdx.y == 1) { in = kin; W = Wk; bias = bk; dst = g_ks; }
    else                      { in = vin; W = Wv; bias = bv; dst = out_v; }

    const int tid = threadIdx.x;

    // Load W (permuted): logical col = 16*cg + 4*c + w -> phys word 4*cg + 32*c + w
    for (int i = tid; i < 16384; i += 256) {
        int k = i >> 7, col = i & 127;
        int cg = col >> 4, c = (col >> 2) & 3, w = col & 3;
        shW[k*128 + cg*4 + c*32 + w] = W[i];
    }
    const size_t base_row = (size_t)blockIdx.x * 64;
    for (int i = tid; i < 2048; i += 256) {        // 64 rows * 32 float4
        int r = i >> 5, c = i & 31;
        float4 v = __ldg((const float4*)(in + base_row*128) + i);
        float* d = shA + r*129 + c*4;
        d[0] = v.x; d[1] = v.y; d[2] = v.z; d[3] = v.w;
    }
    __syncthreads();

    const int r  = tid >> 3;   // 0..31 : rows r and r+32
    const int cg = tid & 7;    // 0..7  : column group == head index

    float acc0[16], acc1[16];
    #pragma unroll
    for (int j = 0; j < 16; j++) {
        float b = __ldg(bias + cg*16 + j);
        acc0[j] = b; acc1[j] = b;
    }

    const float* arow0 = shA + r*129;
    const float* arow1 = shA + (r+32)*129;
    const float* wbase = shW + cg*4;
    #pragma unroll 4
    for (int k = 0; k < 128; k++) {
        const float a0 = arow0[k];
        const float a1 = arow1[k];
        const float4 w0 = *(const float4*)(wbase + k*128);
        const float4 w1 = *(const float4*)(wbase + k*128 + 32);
        const float4 w2 = *(const float4*)(wbase + k*128 + 64);
        const float4 w3 = *(const float4*)(wbase + k*128 + 96);
        acc0[ 0] += a0*w0.x; acc0[ 1] += a0*w0.y; acc0[ 2] += a0*w0.z; acc0[ 3] += a0*w0.w;
        acc0[ 4] += a0*w1.x; acc0[ 5] += a0*w1.y; acc0[ 6] += a0*w1.z; acc0[ 7] += a0*w1.w;
        acc0[ 8] += a0*w2.x; acc0[ 9] += a0*w2.y; acc0[10] += a0*w2.z; acc0[11] += a0*w2.w;
        acc0[12] += a0*w3.x; acc0[13] += a0*w3.y; acc0[14] += a0*w3.z; acc0[15] += a0*w3.w;
        acc1[ 0] += a1*w0.x; acc1[ 1] += a1*w0.y; acc1[ 2] += a1*w0.z; acc1[ 3] += a1*w0.w;
        acc1[ 4] += a1*w1.x; acc1[ 5] += a1*w1.y; acc1[ 6] += a1*w1.z; acc1[ 7] += a1*w1.w;
        acc1[ 8] += a1*w2.x; acc1[ 9] += a1*w2.y; acc1[10] += a1*w2.z; acc1[11] += a1*w2.w;
        acc1[12] += a1*w3.x; acc1[13] += a1*w3.y; acc1[14] += a1*w3.z; acc1[15] += a1*w3.w;
    }

    // Split-head destination: x = h*B + b, h == cg, hd = j
    #pragma unroll
    for (int rr = 0; rr < 2; rr++) {
        const int row = (int)base_row + r + rr*32;
        const int b   = row / (T_*N_);
        const int rem = row - b*(T_*N_);
        const int t   = rem / N_;
        const int n   = rem - t*N_;
        const size_t di = ((((size_t)cg*B_ + b)*T_ + t)*N_ + n)*HD_;
        const float* a = rr ? acc1 : acc0;
        *(float4*)(dst + di     ) = make_float4(a[ 0],a[ 1],a[ 2],a[ 3]);
        *(float4*)(dst + di +  4) = make_float4(a[ 4],a[ 5],a[ 6],a[ 7]);
        *(float4*)(dst + di +  8) = make_float4(a[ 8],a[ 9],a[10],a[11]);
        *(float4*)(dst + di + 12) = make_float4(a[12],a[13],a[14],a[15]);
    }
}

// ---------------------------------------------------------------------------
// Kernel 2: scores + softmax + exact top-k threshold.
// Block: 256 thr (8 warps) = one (x,t), 16 rows (2 rows/warp).
// K tile in smem, row stride 20 floats; lane owns m = lane + 32*j.
// Selection: per-row exact kth key via warp binary search on flipped float
// bits — count_ge with __reduce_add_sync (HW REDUX), early exit when
// count == K (kth = reduce_min of the top set), full 32-bit fallback for
// ties. Both rows' searches are interleaved to overlap the REDUX chains.
// ---------------------------------------------------------------------------
__global__ __launch_bounds__(256, 3) void attn_kernel(
    const float* __restrict__ adp, float* __restrict__ out)
{
    extern __shared__ float sh[];
    float* Ksh = sh;                       // 512 * 20 floats = 40960 B

    const int xt   = blockIdx.y;           // 0..767
    const int tile = blockIdx.x;           // 0..31 : 16 rows each
    const int tid  = threadIdx.x;
    const int lane = tid & 31;
    const int wid  = tid >> 5;
    const size_t xtbase = (size_t)xt * N_;

    // Stage K tile (512 x 16 floats) into padded smem
    const float* gk = g_ks + xtbase * HD_;
    for (int i = tid; i < 2048; i += 256) {
        int m = i >> 2, c = i & 3;
        float4 v = __ldg((const float4*)(gk + (size_t)i*4));
        *(float4*)(Ksh + m*20 + c*4) = v;
    }
    __syncthreads();

    const int n0 = tile*16 + wid*2;
    const float* gq = g_qs + (xtbase + n0) * HD_;

    // ---- score phase: 2 rows x 16 m-values per lane, d split in two sweeps
    float s[2][16];
    #pragma unroll
    for (int r = 0; r < 2; r++)
        #pragma unroll
        for (int j = 0; j < 16; j++) s[r][j] = 0.f;

    #pragma unroll
    for (int hh = 0; hh < 2; hh++) {
        float4 qa[2], qb[2];
        #pragma unroll
        for (int r = 0; r < 2; r++) {
            qa[r] = *(const float4*)(gq + r*16 + 8*hh);
            qb[r] = *(const float4*)(gq + r*16 + 8*hh + 4);
        }
        #pragma unroll
        for (int j = 0; j < 16; j++) {
            const int m = lane + 32*j;
            const float* kr = Ksh + m*20 + 8*hh;
            const float4 ka = *(const float4*)kr;
            const float4 kb = *(const float4*)(kr + 4);
            #pragma unroll
            for (int r = 0; r < 2; r++) {
                s[r][j] += qa[r].x*ka.x + qa[r].y*ka.y + qa[r].z*ka.z + qa[r].w*ka.w
                         + qb[r].x*kb.x + qb[r].y*kb.y + qb[r].z*kb.z + qb[r].w*kb.w;
            }
        }
    }

    // ---- finalize scores -> order-preserving uint keys
    unsigned u[2][16];
    #pragma unroll
    for (int r = 0; r < 2; r++) {
        const float* arow = adp + (n0 + r)*N_;
        #pragma unroll
        for (int j = 0; j < 16; j++)
            u[r][j] = flipf(s[r][j] * 0.25f * __ldg(arow + lane + 32*j));
    }

    // ---- row maxima (for stable exp) via REDUX on keys
    unsigned Mu[2];
    #pragma unroll
    for (int r = 0; r < 2; r++) {
        unsigned m = u[r][0];
        #pragma unroll
        for (int j = 1; j < 16; j++) m = umax(m, u[r][j]);
        Mu[r] = __reduce_max_sync(FULLMASK, m);
    }

    // ---- exact kth-largest key: binary search on bits, both rows interleaved
    unsigned t0 = 0, t1 = 0;
    bool d0 = false, d1 = false;
    #pragma unroll 1
    for (int b = 31; b >= 0; --b) {
        if (!d0) {
            const unsigned tp = t0 | (1u << b);
            int c = 0;
            #pragma unroll
            for (int j = 0; j < 16; j++) c += (u[0][j] >= tp);
            c = __reduce_add_sync(FULLMASK, c);
            if (c >= KTOP_) {
                if (c == KTOP_) {           // top set has exactly K: kth = its min
                    unsigned km = 0xffffffffu;
                    #pragma unroll
                    for (int j = 0; j < 16; j++)
                        if (u[0][j] >= tp) km = umin(km, u[0][j]);
                    t0 = __reduce_min_sync(FULLMASK, km);
                    d0 = true;
                } else t0 = tp;
            }
        }
        if (!d1) {
            const unsigned tp = t1 | (1u << b);
            int c = 0;
            #pragma unroll
            for (int j = 0; j < 16; j++) c += (u[1][j] >= tp);
            c = __reduce_add_sync(FULLMASK, c);
            if (c >= KTOP_) {
                if (c == KTOP_) {
                    unsigned km = 0xffffffffu;
                    #pragma unroll
                    for (int j = 0; j < 16; j++)
                        if (u[1][j] >= tp) km = umin(km, u[1][j]);
                    t1 = __reduce_min_sync(FULLMASK, km);
                    d1 = true;
                } else t1 = tp;
            }
        }
        if (d0 && d1) break;
    }
    const unsigned kth[2] = { t0, t1 };

    // ---- softmax (single exp pass) + keep-mask + write
    #pragma unroll
    for (int r = 0; r < 2; r++) {
        const float Mf = unflipf(Mu[r]);
        unsigned keep = 0; float sum = 0.f;
        float p[16];
        #pragma unroll
        for (int j = 0; j < 16; j++) {
            const unsigned uk = u[r][j];
            if (uk >= kth[r]) keep |= (1u << j);
            const float pv = __expf(unflipf(uk) - Mf);
            sum += pv;
            p[j] = pv;
        }
        #pragma unroll
        for (int d = 16; d; d >>= 1) sum += __shfl_xor_sync(FULLMASK, sum, d);
        const float inv = 1.0f / sum;

        float* orow = out + (xtbase + n0 + r) * N_;
        #pragma unroll
        for (int j = 0; j < 16; j++)
            orow[lane + 32*j] = ((keep >> j) & 1u) ? p[j] * inv : 0.0f;
    }
}

// ---------------------------------------------------------------------------
extern "C" void kernel_launch(void* const* d_in, const int* in_sizes, int n_in,
                              void* d_out, int out_size)
{
    const float* query = (const float*)d_in[0];
    const float* key   = (const float*)d_in[1];
    const float* value = (const float*)d_in[2];
    const float* adp   = (const float*)d_in[3];
    const float* Wq    = (const float*)d_in[4];
    const float* bq    = (const float*)d_in[5];
    const float* Wk    = (const float*)d_in[6];
    const float* bk    = (const float*)d_in[7];
    const float* Wv    = (const float*)d_in[8];
    const float* bv    = (const float*)d_in[9];

    float* out_attn = (float*)d_out;                 // (64,12,512,512)
    float* out_v    = (float*)d_out + ATTN_ELEMS;    // (64,12,512,16)

    const int proj_smem = (16384 + 64*129) * 4;      // 98560 B
    const int attn_smem = (512*20) * 4;              // 40960 B
    cudaFuncSetAttribute(proj_kernel, cudaFuncAttributeMaxDynamicSharedMemorySize, proj_smem);
    cudaFuncSetAttribute(attn_kernel, cudaFuncAttributeMaxDynamicSharedMemorySize, attn_smem);

    proj_kernel<<<dim3((B_*T_*N_)/64, 3), 256, proj_smem>>>(
        query, key, value, Wq, bq, Wk, bk, Wv, bv, out_v);
    attn_kernel<<<dim3(N_/16, X_*T_), 256, attn_smem>>>(adp, out_attn);
    (void)in_sizes; (void)n_in; (void)out_size;
}